// round 11
// baseline (speedup 1.0000x reference)
#include <cuda_runtime.h>
#include <cuda_bf16.h>
#include <cstdint>

// Problem constants (from reference)
#define OUTF    11008
#define INF     4096
#define NGROUPS 32      // INF / 128
#define GSIZE   128
#define BATCH   8

#define THREADS 128
#define WARPS   4
#define NOUT    4                       // output rows per warp
#define OUT_PER_BLOCK (WARPS * NOUT)    // 16
#define GRID_X  (OUTF / OUT_PER_BLOCK)  // 688
#define KSPLIT  2
#define GPER    (NGROUPS / KSPLIT)      // 16 groups per CTA
#define STAGES  4                       // per-warp cp.async pipeline depth

typedef unsigned long long ull;

// ---- packed f32x2 helpers (Blackwell FFMA2; PTX-only) ----
__device__ __forceinline__ ull pack2(uint32_t lo, uint32_t hi) {
    ull r; asm("mov.b64 %0, {%1, %2};" : "=l"(r) : "r"(lo), "r"(hi)); return r;
}
__device__ __forceinline__ ull ffma2(ull a, ull b, ull c) {
    ull d; asm("fma.rn.f32x2 %0, %1, %2, %3;" : "=l"(d) : "l"(a), "l"(b), "l"(c)); return d;
}
__device__ __forceinline__ void unpack2(ull v, float& lo, float& hi) {
    asm("mov.b64 {%0, %1}, %2;" : "=f"(lo), "=f"(hi) : "l"(v));
}
__device__ __forceinline__ float bf16_rn(float v) {
    return __bfloat162float(__float2bfloat16_rn(v));
}
__device__ __forceinline__ ull packf(float lo, float hi) {
    return pack2(__float_as_uint(lo), __float_as_uint(hi));
}

// 128 KB scratch: x transposed, f32. Entry pair (2e, 2e+1), e = (g*4+j)*32+lane,
// holds batches 0-3 / 4-7 of x at k = g*128 + lane*4 + j.
__device__ __align__(16) float4 g_x2[INF * 2];
// Split-K partials (written in full every call -> deterministic)
__device__ float g_part[KSPLIT][BATCH * OUTF];

__global__ void xt2_kernel(const float* __restrict__ x) {
    const int i = blockIdx.x * blockDim.x + threadIdx.x;   // 0..4095
    if (i >= INF) return;
    const int lane = i & 31;
    const int gj   = i >> 5;
    const int g    = gj >> 2;
    const int j    = gj & 3;
    const int k    = g * GSIZE + lane * 4 + j;
    g_x2[2 * i]     = make_float4(x[0 * INF + k], x[1 * INF + k],
                                  x[2 * INF + k], x[3 * INF + k]);
    g_x2[2 * i + 1] = make_float4(x[4 * INF + k], x[5 * INF + k],
                                  x[6 * INF + k], x[7 * INF + k]);
}

__device__ __forceinline__ void cp_async16(void* smem_dst, const void* gmem_src) {
    const uint32_t d = (uint32_t)__cvta_generic_to_shared(smem_dst);
    asm volatile("cp.async.cg.shared.global [%0], [%1], 16;" :: "r"(d), "l"(gmem_src));
}
__device__ __forceinline__ void cp_commit() {
    asm volatile("cp.async.commit_group;");
}

__global__ __launch_bounds__(THREADS)
void wo4l_kernel(const int* __restrict__ qw,       // int32 codes 0..15, [11008][4096]
                 const float2* __restrict__ sz)    // f32 {scale, zero}, [32][11008]
{
    // Warp-private staging: each lane cp.asyncs ONLY the entries it consumes,
    // so cp.async.wait_group alone synchronizes (no barriers anywhere).
    __shared__ __align__(16) int4 sq[WARPS][STAGES][NOUT * 32];

    const int warp = threadIdx.x >> 5;
    const int lane = threadIdx.x & 31;
    const int o0   = blockIdx.x * OUT_PER_BLOCK + warp * NOUT;
    const int g0   = blockIdx.y * GPER;

    const int4* qp = (const int4*)qw;   // lane's k-slice: g*128 + lane*4 + 0..3

    // ---- prologue: stage local groups 0..STAGES-2 ----
    #pragma unroll
    for (int st = 0; st < STAGES - 1; st++) {
        #pragma unroll
        for (int n = 0; n < NOUT; n++)
            cp_async16(&sq[warp][st][n * 32 + lane],
                       &qp[(size_t)(o0 + n) * (INF / 4) + (g0 + st) * 32 + lane]);
        cp_commit();
    }

    ull acc[NOUT][4];                   // [row][batch-pair] packed f32x2
    #pragma unroll
    for (int n = 0; n < NOUT; n++)
        #pragma unroll
        for (int bp = 0; bp < 4; bp++)
            acc[n][bp] = 0ull;

    for (int gi = 0; gi < GPER; ++gi) {
        const int g = g0 + gi;

        // this lane's own copies for stage gi are done when <= STAGES-2 pend
        asm volatile("cp.async.wait_group %0;" :: "n"(STAGES - 2));

        // refill local group gi+STAGES-1 into its stage
        const int gn = gi + STAGES - 1;
        if (gn < GPER) {
            const int st = gn & (STAGES - 1);
            #pragma unroll
            for (int n = 0; n < NOUT; n++)
                cp_async16(&sq[warp][st][n * 32 + lane],
                           &qp[(size_t)(o0 + n) * (INF / 4) + (g0 + gn) * 32 + lane]);
        }
        cp_commit();    // uniform commit keeps group counts aligned in the tail

        // per-group scale/zero (uniform across lanes)
        float s[NOUT], m8s[NOUT];
        __nv_bfloat162 z2[NOUT];
        #pragma unroll
        for (int n = 0; n < NOUT; n++) {
            const float2 v = __ldg(&sz[(size_t)g * OUTF + o0 + n]);
            s[n]   = v.x;
            m8s[n] = -8.0f * v.x;                                    // exact
            z2[n]  = __bfloat162bfloat162(__float2bfloat16_rn(v.y)); // {z,z}
        }

        // q codes from smem — each lane reads exactly what it copied
        const int st = gi & (STAGES - 1);
        int4 qv[NOUT];
        #pragma unroll
        for (int n = 0; n < NOUT; n++)
            qv[n] = sq[warp][st][n * 32 + lane];

        // k-pairs: jp=0 -> (j0,j1)=(0,1), jp=1 -> (2,3)
        #pragma unroll
        for (int jp = 0; jp < 2; ++jp) {
            const int ea = (g * 4 + 2 * jp) * 32 + lane;
            const int eb = ea + 32;
            const float4 a0 = __ldg(&g_x2[2 * ea]);
            const float4 a1 = __ldg(&g_x2[2 * ea + 1]);
            const float4 b0 = __ldg(&g_x2[2 * eb]);
            const float4 b1 = __ldg(&g_x2[2 * eb + 1]);
            ull x2a[4], x2b[4];
            x2a[0] = packf(a0.x, a0.y);  x2a[1] = packf(a0.z, a0.w);
            x2a[2] = packf(a1.x, a1.y);  x2a[3] = packf(a1.z, a1.w);
            x2b[0] = packf(b0.x, b0.y);  x2b[1] = packf(b0.z, b0.w);
            x2b[2] = packf(b1.x, b1.y);  x2b[3] = packf(b1.z, b1.w);

            #pragma unroll
            for (int n = 0; n < NOUT; n++) {
                const int qa = jp ? qv[n].z : qv[n].x;
                const int qb = jp ? qv[n].w : qv[n].y;
                // exact (q-8)*s in f32, RN->bf16 (ref bf16 mul), bf16 add of zero
                const float ta = fmaf((float)qa, s[n], m8s[n]);
                const float tb = fmaf((float)qb, s[n], m8s[n]);
                const __nv_bfloat162 w2 = __hadd2(__floats2bfloat162_rn(ta, tb), z2[n]);
                const uint32_t w2u = *reinterpret_cast<const uint32_t*>(&w2);
                const uint32_t wau = w2u << 16;
                const uint32_t wbu = w2u & 0xffff0000u;
                const ull wa2 = pack2(wau, wau);
                const ull wb2 = pack2(wbu, wbu);
                #pragma unroll
                for (int bp = 0; bp < 4; bp++) {
                    acc[n][bp] = ffma2(wa2, x2a[bp], acc[n][bp]);
                    acc[n][bp] = ffma2(wb2, x2b[bp], acc[n][bp]);
                }
            }
        }
    }

    // unpack and warp-reduce
    float r[NOUT][BATCH];
    #pragma unroll
    for (int n = 0; n < NOUT; n++)
        #pragma unroll
        for (int bp = 0; bp < 4; bp++)
            unpack2(acc[n][bp], r[n][2 * bp], r[n][2 * bp + 1]);

    #pragma unroll
    for (int m = 16; m >= 1; m >>= 1)
        #pragma unroll
        for (int n = 0; n < NOUT; n++)
            #pragma unroll
            for (int b = 0; b < BATCH; b++)
                r[n][b] += __shfl_xor_sync(0xffffffffu, r[n][b], m);

    // store split-K partials (f32)
    #pragma unroll
    for (int b = 0; b < BATCH; b++) {
        if (lane == b) {
            #pragma unroll
            for (int n = 0; n < NOUT; n++)
                g_part[blockIdx.y][(size_t)b * OUTF + o0 + n] = r[n][b];
        }
    }
}

__global__ void final_kernel(float* __restrict__ out) {
    const int i = blockIdx.x * blockDim.x + threadIdx.x;
    if (i < BATCH * OUTF)
        out[i] = bf16_rn(g_part[0][i] + g_part[1][i]);
}

extern "C" void kernel_launch(void* const* d_in, const int* in_sizes, int n_in,
                              void* d_out, int out_size)
{
    // Route inputs by element count (order-proof); fall back to positional.
    const float*  x  = nullptr;   // 8*4096      = 32768
    const int*    qw = nullptr;   // 11008*4096  = 45088768
    const float2* sz = nullptr;   // 32*11008*2  = 704512 scalars
    for (int i = 0; i < n_in; i++) {
        if      (in_sizes[i] == BATCH * INF)         x  = (const float*)d_in[i];
        else if (in_sizes[i] == OUTF * INF)          qw = (const int*)d_in[i];
        else if (in_sizes[i] == NGROUPS * OUTF * 2)  sz = (const float2*)d_in[i];
    }
    if (!x || !qw || !sz) {
        x  = (const float*)d_in[0];
        qw = (const int*)d_in[1];
        sz = (const float2*)d_in[2];
    }
    float* out = (float*)d_out;

    xt2_kernel<<<INF / 128, 128>>>(x);
    wo4l_kernel<<<dim3(GRID_X, KSPLIT), THREADS>>>(qw, sz);
    final_kernel<<<(BATCH * OUTF + 255) / 256, 256>>>(out);
}

// round 12
// speedup vs baseline: 1.1941x; 1.1941x over previous
#include <cuda_runtime.h>
#include <cuda_bf16.h>
#include <cstdint>

// Problem constants (from reference)
#define OUTF    11008
#define INF     4096
#define NGROUPS 32      // INF / 128
#define GSIZE   128
#define BATCH   8

#define THREADS 128
#define WARPS   4
#define NOUT    4                       // output rows per warp
#define OUT_PER_BLOCK (WARPS * NOUT)    // 16
#define GRID    (OUTF / OUT_PER_BLOCK)  // 688
#define STAGES  4                       // per-warp cp.async pipeline depth

typedef unsigned long long ull;

// ---- packed f32x2 helpers (Blackwell FFMA2; PTX-only) ----
__device__ __forceinline__ ull pack2(uint32_t lo, uint32_t hi) {
    ull r; asm("mov.b64 %0, {%1, %2};" : "=l"(r) : "r"(lo), "r"(hi)); return r;
}
__device__ __forceinline__ ull ffma2(ull a, ull b, ull c) {
    ull d; asm("fma.rn.f32x2 %0, %1, %2, %3;" : "=l"(d) : "l"(a), "l"(b), "l"(c)); return d;
}
__device__ __forceinline__ void unpack2(ull v, float& lo, float& hi) {
    asm("mov.b64 {%0, %1}, %2;" : "=f"(lo), "=f"(hi) : "l"(v));
}
__device__ __forceinline__ float bf16_rn(float v) {
    return __bfloat162float(__float2bfloat16_rn(v));
}

// 64 KB scratch: x transposed/packed. Entry i = (g*4+j)*32 + lane holds
// all 8 batches (bf16) of x at k = g*128 + lane*4 + j.
__device__ __align__(16) uint4 g_xt[INF];

__global__ void xt_kernel(const float* __restrict__ x) {
    const int i = blockIdx.x * blockDim.x + threadIdx.x;   // 0..4095
    if (i >= INF) return;
    const int lane = i & 31;
    const int gj   = i >> 5;
    const int g    = gj >> 2;
    const int j    = gj & 3;
    const int k    = g * GSIZE + lane * 4 + j;
    uint32_t u[4];
    #pragma unroll
    for (int bp = 0; bp < 4; bp++) {
        const float f0 = x[(size_t)(2 * bp) * INF + k];
        const float f1 = x[(size_t)(2 * bp + 1) * INF + k];
        __nv_bfloat162 p = __floats2bfloat162_rn(f0, f1);   // exact: values are bf16-valued
        u[bp] = *reinterpret_cast<uint32_t*>(&p);           // {b_even lo16, b_odd hi16}
    }
    g_xt[i] = make_uint4(u[0], u[1], u[2], u[3]);
}

__device__ __forceinline__ void cp_async16(void* smem_dst, const void* gmem_src) {
    const uint32_t d = (uint32_t)__cvta_generic_to_shared(smem_dst);
    asm volatile("cp.async.cg.shared.global [%0], [%1], 16;" :: "r"(d), "l"(gmem_src));
}
__device__ __forceinline__ void cp_commit() {
    asm volatile("cp.async.commit_group;");
}

__global__ __launch_bounds__(THREADS)
void wo4l_kernel(const int* __restrict__ qw,       // int32 codes 0..15, [11008][4096]
                 const float2* __restrict__ sz,    // f32 {scale, zero}, [32][11008]
                 float* __restrict__ out)          // f32 (bf16-valued), [8][11008]
{
    // Warp-private staging: each lane cp.asyncs ONLY the entries it consumes,
    // so cp.async.wait_group alone synchronizes — no __syncthreads anywhere.
    __shared__ __align__(16) int4 sq[WARPS][STAGES][NOUT * 32];   // 32 KB

    const int warp = threadIdx.x >> 5;
    const int lane = threadIdx.x & 31;
    const int o0   = blockIdx.x * OUT_PER_BLOCK + warp * NOUT;

    const int4* qp = (const int4*)qw;   // lane's k-slice: g*128 + lane*4 + 0..3

    // ---- prologue: stage groups 0..STAGES-2 ----
    #pragma unroll
    for (int st = 0; st < STAGES - 1; st++) {
        #pragma unroll
        for (int n = 0; n < NOUT; n++)
            cp_async16(&sq[warp][st][n * 32 + lane],
                       &qp[(size_t)(o0 + n) * (INF / 4) + st * 32 + lane]);
        cp_commit();
    }

    ull acc[NOUT][4];                   // [row][batch-pair] packed f32x2
    #pragma unroll
    for (int n = 0; n < NOUT; n++)
        #pragma unroll
        for (int bp = 0; bp < 4; bp++)
            acc[n][bp] = 0ull;

    for (int g = 0; g < NGROUPS; ++g) {
        // this lane's own copies for stage g are done when <= STAGES-2 pend
        asm volatile("cp.async.wait_group %0;" :: "n"(STAGES - 2));

        // refill group g+STAGES-1 into its stage
        const int gn = g + STAGES - 1;
        if (gn < NGROUPS) {
            const int st = gn & (STAGES - 1);
            #pragma unroll
            for (int n = 0; n < NOUT; n++)
                cp_async16(&sq[warp][st][n * 32 + lane],
                           &qp[(size_t)(o0 + n) * (INF / 4) + gn * 32 + lane]);
        }
        cp_commit();    // uniform commit keeps group counts aligned in the tail

        // per-group scale/zero (uniform across lanes)
        float s[NOUT], m8s[NOUT];
        __nv_bfloat162 z2[NOUT];
        #pragma unroll
        for (int n = 0; n < NOUT; n++) {
            const float2 v = __ldg(&sz[(size_t)g * OUTF + o0 + n]);
            s[n]   = v.x;
            m8s[n] = -8.0f * v.x;                                    // exact
            z2[n]  = __bfloat162bfloat162(__float2bfloat16_rn(v.y)); // {z,z}
        }

        // q codes from smem — each lane reads exactly what it copied
        const int st = g & (STAGES - 1);
        int4 qv[NOUT];
        #pragma unroll
        for (int n = 0; n < NOUT; n++)
            qv[n] = sq[warp][st][n * 32 + lane];

        // k-pairs: jp=0 -> (j0,j1)=(0,1), jp=1 -> (2,3)
        #pragma unroll
        for (int jp = 0; jp < 2; ++jp) {
            // x for the two k's: one LDG.128 each = all 8 batches (bf16-packed)
            const uint4 xa = __ldg(&g_xt[(g * 4 + 2 * jp)     * 32 + lane]);
            const uint4 xb = __ldg(&g_xt[(g * 4 + 2 * jp + 1) * 32 + lane]);
            ull x2a[4], x2b[4];
            {
                const uint32_t ua[4] = {xa.x, xa.y, xa.z, xa.w};
                const uint32_t ub[4] = {xb.x, xb.y, xb.z, xb.w};
                #pragma unroll
                for (int bp = 0; bp < 4; bp++) {
                    x2a[bp] = pack2(ua[bp] << 16, ua[bp] & 0xffff0000u);
                    x2b[bp] = pack2(ub[bp] << 16, ub[bp] & 0xffff0000u);
                }
            }
            #pragma unroll
            for (int n = 0; n < NOUT; n++) {
                const int qa = jp ? qv[n].z : qv[n].x;
                const int qb = jp ? qv[n].w : qv[n].y;
                // exact (q-8)*s in f32, RN->bf16 (ref bf16 mul), bf16 add of zero
                const float ta = fmaf((float)qa, s[n], m8s[n]);
                const float tb = fmaf((float)qb, s[n], m8s[n]);
                const __nv_bfloat162 w2 = __hadd2(__floats2bfloat162_rn(ta, tb), z2[n]);
                const uint32_t w2u = *reinterpret_cast<const uint32_t*>(&w2);
                const uint32_t wau = w2u << 16;
                const uint32_t wbu = w2u & 0xffff0000u;
                const ull wa2 = pack2(wau, wau);
                const ull wb2 = pack2(wbu, wbu);
                #pragma unroll
                for (int bp = 0; bp < 4; bp++) {
                    acc[n][bp] = ffma2(wa2, x2a[bp], acc[n][bp]);
                    acc[n][bp] = ffma2(wb2, x2b[bp], acc[n][bp]);
                }
            }
        }
    }

    // unpack and warp-reduce
    float r[NOUT][BATCH];
    #pragma unroll
    for (int n = 0; n < NOUT; n++)
        #pragma unroll
        for (int bp = 0; bp < 4; bp++)
            unpack2(acc[n][bp], r[n][2 * bp], r[n][2 * bp + 1]);

    #pragma unroll
    for (int m = 16; m >= 1; m >>= 1)
        #pragma unroll
        for (int n = 0; n < NOUT; n++)
            #pragma unroll
            for (int b = 0; b < BATCH; b++)
                r[n][b] += __shfl_xor_sync(0xffffffffu, r[n][b], m);

    // epilogue: lane b stores batch b; bf16-round (ref output is bf16-valued)
    #pragma unroll
    for (int b = 0; b < BATCH; b++) {
        if (lane == b) {
            #pragma unroll
            for (int n = 0; n < NOUT; n++)
                out[(size_t)b * OUTF + o0 + n] = bf16_rn(r[n][b]);
        }
    }
}

extern "C" void kernel_launch(void* const* d_in, const int* in_sizes, int n_in,
                              void* d_out, int out_size)
{
    // Route inputs by element count (order-proof); fall back to positional.
    const float*  x  = nullptr;   // 8*4096      = 32768
    const int*    qw = nullptr;   // 11008*4096  = 45088768
    const float2* sz = nullptr;   // 32*11008*2  = 704512 scalars
    for (int i = 0; i < n_in; i++) {
        if      (in_sizes[i] == BATCH * INF)         x  = (const float*)d_in[i];
        else if (in_sizes[i] == OUTF * INF)          qw = (const int*)d_in[i];
        else if (in_sizes[i] == NGROUPS * OUTF * 2)  sz = (const float2*)d_in[i];
    }
    if (!x || !qw || !sz) {
        x  = (const float*)d_in[0];
        qw = (const int*)d_in[1];
        sz = (const float2*)d_in[2];
    }
    float* out = (float*)d_out;

    xt_kernel<<<INF / 128, 128>>>(x);
    wo4l_kernel<<<GRID, THREADS>>>(qw, sz, out);
}